// round 3
// baseline (speedup 1.0000x reference)
#include <cuda_runtime.h>
#include <math.h>

// Problem constants
#define B_   64
#define T_   512
#define F_   513
#define H_   50
#define G_   200        // 4*H
#define M_   32768      // B*T

// Scratch (allocation-free rule: use __device__ globals)
__device__ float g_xg[M_ * G_];   // 26.2 MB: pre-activations x@W_ih^T + b_ih + b_hh
__device__ float g_hs[M_ * H_];   // 6.6 MB: hidden states

// ---------------------------------------------------------------------------
// Kernel A: xg = X (32768 x 513) @ W_ih^T (513 x 200) + (b_ih + b_hh)
// Block tile 256(M) x 40(N), K-chunks of 32. Thread tile 8x5, 256 threads.
// ---------------------------------------------------------------------------
__global__ __launch_bounds__(256) void xg_gemm_kernel(
    const float* __restrict__ x,
    const float* __restrict__ Wih,
    const float* __restrict__ bih,
    const float* __restrict__ bhh)
{
    __shared__ float Xs[256 * 33];  // pad 33: conflict-free row reads
    __shared__ float Ws[32 * 41];   // pad 41: conflict-free col reads

    const int tid = threadIdx.x;
    const int m0  = blockIdx.x * 256;
    const int n0  = blockIdx.y * 40;
    const int tx  = tid & 7;        // 8 col-groups
    const int ty  = tid >> 3;       // 32 row-groups
    const int r0  = ty * 8;
    const int c0  = tx * 5;

    float acc[8][5];
#pragma unroll
    for (int i = 0; i < 8; i++)
#pragma unroll
        for (int j = 0; j < 5; j++) acc[i][j] = 0.f;

    for (int kb = 0; kb < 17; kb++) {       // ceil(513/32)
        const int kbase = kb * 32;

        // Load X tile: 256x32, coalesced (consecutive tid -> consecutive k)
#pragma unroll
        for (int i = 0; i < 32; i++) {
            int e = tid + 256 * i;
            int r = e >> 5, k = e & 31;
            int kk = kbase + k;
            Xs[r * 33 + k] = (kk < F_) ? x[(m0 + r) * F_ + kk] : 0.f;
        }
        // Load W tile transposed: Ws[k][c] = Wih[n0+c][kbase+k]
#pragma unroll
        for (int i = 0; i < 5; i++) {
            int e = tid + 256 * i;
            int c = e >> 5, k = e & 31;
            int kk = kbase + k;
            Ws[k * 41 + c] = (kk < F_) ? Wih[(n0 + c) * F_ + kk] : 0.f;
        }
        __syncthreads();

#pragma unroll 8
        for (int k = 0; k < 32; k++) {
            float a[8], w[5];
#pragma unroll
            for (int i = 0; i < 8; i++) a[i] = Xs[(r0 + i) * 33 + k];
#pragma unroll
            for (int j = 0; j < 5; j++) w[j] = Ws[k * 41 + c0 + j];
#pragma unroll
            for (int i = 0; i < 8; i++)
#pragma unroll
                for (int j = 0; j < 5; j++) acc[i][j] += a[i] * w[j];
        }
        __syncthreads();
    }

    // Epilogue: add both biases (b_ih in xg + b_hh in step <=> sum)
#pragma unroll
    for (int j = 0; j < 5; j++) {
        const int col = n0 + c0 + j;
        const float bsum = bih[col] + bhh[col];
#pragma unroll
        for (int i = 0; i < 8; i++) {
            g_xg[(m0 + r0 + i) * G_ + col] = acc[i][j] + bsum;
        }
    }
}

// ---------------------------------------------------------------------------
// Kernel B: LSTM recurrence over the BATCH axis.
// 512 blocks (one per timestep t = chain), 64 sequential steps (b = 0..63).
// W_hh resident in SMEM (stride 51 -> conflict-free), h/c in SMEM.
// ---------------------------------------------------------------------------
__global__ __launch_bounds__(256) void lstm_rec_kernel(
    const float* __restrict__ Whh)
{
    __shared__ float Wsh[G_ * 51];
    __shared__ float h_sh[H_];
    __shared__ float c_sh[H_];
    __shared__ float gsh[G_];

    const int tid = threadIdx.x;
    const int t   = blockIdx.x;

    // Stage W_hh (200 x 50) into padded SMEM
    for (int e = tid; e < G_ * H_; e += 256) {
        int j = e / H_, k = e - j * H_;
        Wsh[j * 51 + k] = Whh[e];
    }
    if (tid < H_) { h_sh[tid] = 0.f; c_sh[tid] = 0.f; }
    __syncthreads();

    for (int b = 0; b < B_; b++) {
        const int row = b * T_ + t;

        if (tid < G_) {
            float a0 = 0.f, a1 = 0.f;
            const float* wr = &Wsh[tid * 51];
#pragma unroll
            for (int k = 0; k < H_; k += 2) {
                a0 += wr[k]     * h_sh[k];
                a1 += wr[k + 1] * h_sh[k + 1];
            }
            gsh[tid] = g_xg[row * G_ + tid] + a0 + a1;
        }
        __syncthreads();

        if (tid < H_) {
            const float iv = gsh[tid];
            const float fv = gsh[tid + 50];
            const float gg = gsh[tid + 100];
            const float ov = gsh[tid + 150];
            const float si = 1.f / (1.f + expf(-iv));
            const float sf = 1.f / (1.f + expf(-fv));
            const float so = 1.f / (1.f + expf(-ov));
            const float tg = tanhf(gg);
            const float cn = sf * c_sh[tid] + si * tg;
            c_sh[tid] = cn;
            const float hn = so * tanhf(cn);
            h_sh[tid] = hn;
            g_hs[row * H_ + tid] = hn;
        }
        __syncthreads();   // protects h_sh/c_sh for next step's reads
    }
}

// ---------------------------------------------------------------------------
// Kernel C: out = hs (32768 x 50) @ W_out^T (50 x 513) + b_out
// Block tile 64x64, thread tile 4x4, K=50 fully staged in SMEM.
// ---------------------------------------------------------------------------
__global__ __launch_bounds__(256) void out_gemm_kernel(
    const float* __restrict__ Wout,
    const float* __restrict__ bout,
    float* __restrict__ out)
{
    __shared__ float Hs[64 * 52];   // Hs[r][k]
    __shared__ float Wt[50 * 65];   // Wt[k][c]

    const int tid = threadIdx.x;
    const int m0  = blockIdx.x * 64;
    const int n0  = blockIdx.y * 64;

    for (int e = tid; e < 64 * H_; e += 256) {
        int r = e / H_, k = e - r * H_;
        Hs[r * 52 + k] = g_hs[(m0 + r) * H_ + k];
    }
    for (int e = tid; e < 64 * H_; e += 256) {
        int c = e / H_, k = e - c * H_;
        int col = n0 + c;
        Wt[k * 65 + c] = (col < F_) ? Wout[col * H_ + k] : 0.f;
    }
    __syncthreads();

    const int tx = tid & 15;
    const int ty = tid >> 4;
    const int r0 = ty * 4;
    const int c0 = tx * 4;

    float acc[4][4];
#pragma unroll
    for (int i = 0; i < 4; i++)
#pragma unroll
        for (int j = 0; j < 4; j++) acc[i][j] = 0.f;

#pragma unroll 10
    for (int k = 0; k < H_; k++) {
        float a[4], w[4];
#pragma unroll
        for (int i = 0; i < 4; i++) a[i] = Hs[(r0 + i) * 52 + k];
#pragma unroll
        for (int j = 0; j < 4; j++) w[j] = Wt[k * 65 + c0 + j];
#pragma unroll
        for (int i = 0; i < 4; i++)
#pragma unroll
            for (int j = 0; j < 4; j++) acc[i][j] += a[i] * w[j];
    }

#pragma unroll
    for (int j = 0; j < 4; j++) {
        const int col = n0 + c0 + j;
        if (col < F_) {
            const float bb = bout[col];
#pragma unroll
            for (int i = 0; i < 4; i++) {
                out[(m0 + r0 + i) * F_ + col] = acc[i][j] + bb;
            }
        }
    }
}

// ---------------------------------------------------------------------------
// Launch: inputs per metadata order: x, W_ih, W_hh, b_ih, b_hh, W_out, b_out
// ---------------------------------------------------------------------------
extern "C" void kernel_launch(void* const* d_in, const int* in_sizes, int n_in,
                              void* d_out, int out_size)
{
    const float* x    = (const float*)d_in[0];
    const float* Wih  = (const float*)d_in[1];
    const float* Whh  = (const float*)d_in[2];
    const float* bih  = (const float*)d_in[3];
    const float* bhh  = (const float*)d_in[4];
    const float* Wout = (const float*)d_in[5];
    const float* bout = (const float*)d_in[6];
    float* out = (float*)d_out;

    // A: xg GEMM.  grid (32768/256, 200/40)
    dim3 gA(M_ / 256, G_ / 40);
    xg_gemm_kernel<<<gA, 256>>>(x, Wih, bih, bhh);

    // B: recurrence. one block per chain t
    lstm_rec_kernel<<<T_, 256>>>(Whh);

    // C: output GEMM. grid (32768/64, ceil(513/64))
    dim3 gC(M_ / 64, (F_ + 63) / 64);
    out_gemm_kernel<<<gC, 256>>>(Wout, bout, out);
}

// round 4
// speedup vs baseline: 1.2085x; 1.2085x over previous
#include <cuda_runtime.h>
#include <math.h>

// Problem constants
#define B_   64
#define T_   512
#define F_   513
#define H_   50
#define G_   200        // 4*H
#define M_   32768      // B*T

// Scratch (allocation-free rule: __device__ globals)
__device__ float g_xg[M_ * G_];   // 26.2 MB: x@W_ih^T + b_ih + b_hh
__device__ float g_hs[M_ * H_];   // 6.6 MB: hidden states

// ---------------------------------------------------------------------------
// tf32 split + mma helpers
// ---------------------------------------------------------------------------
__device__ __forceinline__ void tf32_split(float x, unsigned &hi, unsigned &lo) {
    unsigned h;
    asm("cvt.rna.tf32.f32 %0, %1;" : "=r"(h) : "f"(x));
    float r = x - __uint_as_float(h);
    unsigned l;
    asm("cvt.rna.tf32.f32 %0, %1;" : "=r"(l) : "f"(r));
    hi = h; lo = l;
}

__device__ __forceinline__ void mma8(float* d, const unsigned* a,
                                     unsigned b0, unsigned b1) {
    asm volatile(
        "mma.sync.aligned.m16n8k8.row.col.f32.tf32.tf32.f32 "
        "{%0,%1,%2,%3}, {%4,%5,%6,%7}, {%8,%9}, {%0,%1,%2,%3};\n"
        : "+f"(d[0]), "+f"(d[1]), "+f"(d[2]), "+f"(d[3])
        : "r"(a[0]), "r"(a[1]), "r"(a[2]), "r"(a[3]), "r"(b0), "r"(b1));
}

// ---------------------------------------------------------------------------
// Kernel A: xg = X (32768 x 513) @ W_ih^T (513 x 200) + (b_ih + b_hh)
// tf32 mma, block tile 128(M) x 40(N), K-chunks of 32, 8 warps.
// Warp w owns rows [16w,16w+16), all 40 cols (5 n8 tiles).
// Tiles stored [row][k] stride 36 -> fragment LDS bank = (4g+c): conflict-free.
// ---------------------------------------------------------------------------
#define SA 36

__global__ __launch_bounds__(256) void xg_mma_kernel(
    const float* __restrict__ x,
    const float* __restrict__ Wih,
    const float* __restrict__ bih,
    const float* __restrict__ bhh)
{
    __shared__ float As[128 * SA];
    __shared__ float Bs[40 * SA];

    const int tid  = threadIdx.x;
    const int lane = tid & 31;
    const int w    = tid >> 5;
    const int m0   = blockIdx.x * 128;
    const int n0   = blockIdx.y * 40;
    const int g    = lane >> 2;   // 0..7
    const int c    = lane & 3;    // 0..3
    const int rw   = w * 16;

    float d[5][4];
#pragma unroll
    for (int nt = 0; nt < 5; nt++)
#pragma unroll
        for (int i = 0; i < 4; i++) d[nt][i] = 0.f;

    for (int kb = 0; kb < 17; kb++) {
        const int kbase = kb * 32;

        // A tile 128x32, coalesced over k
#pragma unroll
        for (int i = 0; i < 16; i++) {
            int e = tid + 256 * i;
            int r = e >> 5, k = e & 31;
            int kk = kbase + k;
            As[r * SA + k] = (kk < F_) ? x[(m0 + r) * F_ + kk] : 0.f;
        }
        // B tile 40x32 (Wih rows n0..n0+39), coalesced over k
#pragma unroll
        for (int i = 0; i < 5; i++) {
            int e = tid + 256 * i;
            int n = e >> 5, k = e & 31;
            int kk = kbase + k;
            Bs[n * SA + k] = (kk < F_) ? Wih[(n0 + n) * F_ + kk] : 0.f;
        }
        __syncthreads();

#pragma unroll
        for (int ks = 0; ks < 4; ks++) {
            const int k0 = ks * 8;
            unsigned ah[4], al[4];
            {
                float a0 = As[(rw + g)     * SA + k0 + c];
                float a1 = As[(rw + g + 8) * SA + k0 + c];
                float a2 = As[(rw + g)     * SA + k0 + c + 4];
                float a3 = As[(rw + g + 8) * SA + k0 + c + 4];
                tf32_split(a0, ah[0], al[0]);
                tf32_split(a1, ah[1], al[1]);
                tf32_split(a2, ah[2], al[2]);
                tf32_split(a3, ah[3], al[3]);
            }
#pragma unroll
            for (int nt = 0; nt < 5; nt++) {
                float b0f = Bs[(nt * 8 + g) * SA + k0 + c];
                float b1f = Bs[(nt * 8 + g) * SA + k0 + c + 4];
                unsigned bh0, bl0, bh1, bl1;
                tf32_split(b0f, bh0, bl0);
                tf32_split(b1f, bh1, bl1);
                mma8(d[nt], ah, bh0, bh1);   // hi*hi
                mma8(d[nt], al, bh0, bh1);   // lo*hi
                mma8(d[nt], ah, bl0, bl1);   // hi*lo
            }
        }
        __syncthreads();
    }

    // Epilogue: + (b_ih + b_hh), float2 stores (col even, pitch 200 even)
#pragma unroll
    for (int nt = 0; nt < 5; nt++) {
        int col = n0 + nt * 8 + 2 * c;
        float bs0 = bih[col] + bhh[col];
        float bs1 = bih[col + 1] + bhh[col + 1];
        int row0 = m0 + rw + g;
        float2 v0 = make_float2(d[nt][0] + bs0, d[nt][1] + bs1);
        float2 v1 = make_float2(d[nt][2] + bs0, d[nt][3] + bs1);
        *(float2*)&g_xg[row0 * G_ + col]       = v0;
        *(float2*)&g_xg[(row0 + 8) * G_ + col] = v1;
    }
}

// ---------------------------------------------------------------------------
// Kernel B: LSTM recurrence along the BATCH axis (512 chains, 64 steps).
// W_hh resident in SMEM (stride 51 -> conflict-free permutation), h/c in SMEM.
// Next step's xg row is prefetched before the current dot (hides DRAM lat).
// Activations via __expf (2-ulp), overflow-safe tanh.
// ---------------------------------------------------------------------------
__device__ __forceinline__ float fast_sigmoid(float x) {
    return 1.f / (1.f + __expf(-x));
}
__device__ __forceinline__ float fast_tanh(float x) {
    float ax = fabsf(x);
    float e  = __expf(2.f * ax);          // inf for large ax -> 2/(1+inf)=0
    float t  = 1.f - 2.f / (1.f + e);
    return copysignf(t, x);
}

__global__ __launch_bounds__(256) void lstm_rec_kernel(
    const float* __restrict__ Whh)
{
    __shared__ float Wsh[G_ * 51];
    __shared__ float h_sh[H_];
    __shared__ float c_sh[H_];
    __shared__ float gsh[G_];

    const int tid = threadIdx.x;
    const int t   = blockIdx.x;

    for (int e = tid; e < G_ * H_; e += 256) {
        int j = e / H_, k = e - j * H_;
        Wsh[j * 51 + k] = Whh[e];
    }
    if (tid < H_) { h_sh[tid] = 0.f; c_sh[tid] = 0.f; }
    __syncthreads();

    float pre = (tid < G_) ? g_xg[t * G_ + tid] : 0.f;  // row(b=0) = t

    for (int b = 0; b < B_; b++) {
        // Prefetch next step's xg row BEFORE the dot — no dependency on h,
        // DRAM latency overlaps the dot + activation chain.
        float nxt = 0.f;
        if (b + 1 < B_ && tid < G_)
            nxt = __ldg(&g_xg[((b + 1) * T_ + t) * G_ + tid]);

        if (tid < G_) {
            float a0 = 0.f, a1 = 0.f;
            const float* wr = &Wsh[tid * 51];
#pragma unroll
            for (int k = 0; k < H_; k += 2) {
                a0 += wr[k]     * h_sh[k];
                a1 += wr[k + 1] * h_sh[k + 1];
            }
            gsh[tid] = pre + a0 + a1;
        }
        __syncthreads();

        if (tid < H_) {
            const float si = fast_sigmoid(gsh[tid]);
            const float sf = fast_sigmoid(gsh[tid + 50]);
            const float tg = fast_tanh(gsh[tid + 100]);
            const float so = fast_sigmoid(gsh[tid + 150]);
            const float cn = sf * c_sh[tid] + si * tg;
            c_sh[tid] = cn;
            const float hn = so * fast_tanh(cn);
            h_sh[tid] = hn;
            g_hs[(b * T_ + t) * H_ + tid] = hn;
        }
        __syncthreads();
        pre = nxt;
    }
}

// ---------------------------------------------------------------------------
// Kernel C: out = hs (32768 x 50) @ W_out^T (50 x 513) + b_out
// tf32 mma, block tile 128 x 40, K padded 50->56, single SMEM stage.
// [row][k] stride 60 -> fragment LDS bank = (28g+c): conflict-free.
// ---------------------------------------------------------------------------
#define SC 60
#define KC 56

__global__ __launch_bounds__(256) void out_mma_kernel(
    const float* __restrict__ Wout,
    const float* __restrict__ bout,
    float* __restrict__ out)
{
    __shared__ float As[128 * SC];
    __shared__ float Bs[40 * SC];

    const int tid  = threadIdx.x;
    const int lane = tid & 31;
    const int w    = tid >> 5;
    const int m0   = blockIdx.x * 128;
    const int n0   = blockIdx.y * 40;
    const int g    = lane >> 2;
    const int c    = lane & 3;
    const int rw   = w * 16;

    // hs tile 128x56 (k 50..55 zero)
    for (int e = tid; e < 128 * KC; e += 256) {
        int m = e / KC, k = e - m * KC;
        As[m * SC + k] = (k < H_) ? g_hs[(m0 + m) * H_ + k] : 0.f;
    }
    // Wout tile 40x56 with column guard
    for (int e = tid; e < 40 * KC; e += 256) {
        int n = e / KC, k = e - n * KC;
        int col = n0 + n;
        Bs[n * SC + k] = (col < F_ && k < H_) ? Wout[col * H_ + k] : 0.f;
    }
    __syncthreads();

    float d[5][4];
#pragma unroll
    for (int nt = 0; nt < 5; nt++)
#pragma unroll
        for (int i = 0; i < 4; i++) d[nt][i] = 0.f;

#pragma unroll
    for (int ks = 0; ks < 7; ks++) {
        const int k0 = ks * 8;
        unsigned ah[4], al[4];
        {
            float a0 = As[(rw + g)     * SC + k0 + c];
            float a1 = As[(rw + g + 8) * SC + k0 + c];
            float a2 = As[(rw + g)     * SC + k0 + c + 4];
            float a3 = As[(rw + g + 8) * SC + k0 + c + 4];
            tf32_split(a0, ah[0], al[0]);
            tf32_split(a1, ah[1], al[1]);
            tf32_split(a2, ah[2], al[2]);
            tf32_split(a3, ah[3], al[3]);
        }
#pragma unroll
        for (int nt = 0; nt < 5; nt++) {
            float b0f = Bs[(nt * 8 + g) * SC + k0 + c];
            float b1f = Bs[(nt * 8 + g) * SC + k0 + c + 4];
            unsigned bh0, bl0, bh1, bl1;
            tf32_split(b0f, bh0, bl0);
            tf32_split(b1f, bh1, bl1);
            mma8(d[nt], ah, bh0, bh1);
            mma8(d[nt], al, bh0, bh1);
            mma8(d[nt], ah, bl0, bl1);
        }
    }

    // Epilogue: + b_out, scalar stores (pitch 513 is odd -> no float2 align)
#pragma unroll
    for (int nt = 0; nt < 5; nt++) {
        int col = n0 + nt * 8 + 2 * c;
        int row0 = m0 + rw + g;
        if (col < F_) {
            float bb = bout[col];
            out[row0 * F_ + col]       = d[nt][0] + bb;
            out[(row0 + 8) * F_ + col] = d[nt][2] + bb;
        }
        if (col + 1 < F_) {
            float bb = bout[col + 1];
            out[row0 * F_ + col + 1]       = d[nt][1] + bb;
            out[(row0 + 8) * F_ + col + 1] = d[nt][3] + bb;
        }
    }
}

// ---------------------------------------------------------------------------
// Launch: inputs: x, W_ih, W_hh, b_ih, b_hh, W_out, b_out
// ---------------------------------------------------------------------------
extern "C" void kernel_launch(void* const* d_in, const int* in_sizes, int n_in,
                              void* d_out, int out_size)
{
    const float* x    = (const float*)d_in[0];
    const float* Wih  = (const float*)d_in[1];
    const float* Whh  = (const float*)d_in[2];
    const float* bih  = (const float*)d_in[3];
    const float* bhh  = (const float*)d_in[4];
    const float* Wout = (const float*)d_in[5];
    const float* bout = (const float*)d_in[6];
    float* out = (float*)d_out;

    dim3 gA(M_ / 128, G_ / 40);            // (256, 5)
    xg_mma_kernel<<<gA, 256>>>(x, Wih, bih, bhh);

    lstm_rec_kernel<<<T_, 256>>>(Whh);

    dim3 gC(M_ / 128, (F_ + 39) / 40);     // (256, 13)
    out_mma_kernel<<<gC, 256>>>(Wout, bout, out);
}